// round 2
// baseline (speedup 1.0000x reference)
#include <cuda_runtime.h>
#include <math.h>

#define NN   100000
#define D    128
#define EMAX 1600000

// ---------------- scratch (device globals; no allocation allowed) ----------------
__device__ int    g_cnt[2][NN];        // in-degree counts
__device__ int    g_fill[2][NN];       // CSR fill cursors
__device__ int    g_rowptr[2][NN + 1]; // CSR row pointers (by dst)
__device__ int    g_esrc[2][EMAX];     // CSR: src node per edge slot
__device__ float  g_norm[2][NN];       // D^-1/2 normalization
__device__ float  g_feat[2][NN * D];   // current layer features
__device__ float  g_h[2][NN * D];      // post-aggregation residual features
__device__ double g_sum[2][D];
__device__ double g_sumsq[2][D];
__device__ float  g_mean[2][D];
__device__ float  g_rstd[2][D];

// ---------------- prep kernels ----------------
__global__ void k_init(int n) {
    int i = blockIdx.x * blockDim.x + threadIdx.x;
    if (i < n) {
        g_cnt[0][i] = 0; g_cnt[1][i] = 0;
        g_fill[0][i] = 0; g_fill[1][i] = 0;
    }
    if (i < D) {
        g_sum[0][i] = 0.0; g_sum[1][i] = 0.0;
        g_sumsq[0][i] = 0.0; g_sumsq[1][i] = 0.0;
    }
}

__global__ void k_hist(const int* __restrict__ dst1, const int* __restrict__ dst2, int E) {
    int i = blockIdx.x * blockDim.x + threadIdx.x;
    if (i < E) {
        atomicAdd(&g_cnt[0][dst1[i]], 1);
    } else if (i < 2 * E) {
        atomicAdd(&g_cnt[1][dst2[i - E]], 1);
    }
}

// one block per graph; warp-shuffle scan per 1024-tile; also emits norm
__global__ void k_scan(int n) {
    int g = blockIdx.x;
    __shared__ int warp_tot[32];
    __shared__ int s_off;
    int lane = threadIdx.x & 31;
    int wid = threadIdx.x >> 5;
    if (threadIdx.x == 0) s_off = 0;
    __syncthreads();
    for (int base = 0; base < n; base += 1024) {
        int i = base + threadIdx.x;
        int v = (i < n) ? g_cnt[g][i] : 0;
        if (i < n) g_norm[g][i] = rsqrtf((float)max(v, 1));
        // inclusive warp scan
        int x = v;
#pragma unroll
        for (int ofs = 1; ofs < 32; ofs <<= 1) {
            int t = __shfl_up_sync(0xFFFFFFFFu, x, ofs);
            if (lane >= ofs) x += t;
        }
        if (lane == 31) warp_tot[wid] = x;
        __syncthreads();
        // warp 0 scans the 32 warp totals (exclusive)
        if (wid == 0) {
            int wt = warp_tot[lane];
            int y = wt;
#pragma unroll
            for (int ofs = 1; ofs < 32; ofs <<= 1) {
                int t = __shfl_up_sync(0xFFFFFFFFu, y, ofs);
                if (lane >= ofs) y += t;
            }
            warp_tot[lane] = y - wt;  // exclusive prefix of warp totals
            if (lane == 31) warp_tot[31] = y - wt;  // keep exclusive; tile total handled below
        }
        __syncthreads();
        int excl = s_off + warp_tot[wid] + (x - v);
        if (i < n) g_rowptr[g][i] = excl;
        __syncthreads();
        if (threadIdx.x == 1023) s_off = excl + v;
        __syncthreads();
    }
    if (threadIdx.x == 0) g_rowptr[g][n] = s_off;
}

__global__ void k_fill(const int* __restrict__ src1, const int* __restrict__ dst1,
                       const int* __restrict__ src2, const int* __restrict__ dst2, int E) {
    int i = blockIdx.x * blockDim.x + threadIdx.x;
    if (i < E) {
        int d = dst1[i];
        int pos = g_rowptr[0][d] + atomicAdd(&g_fill[0][d], 1);
        g_esrc[0][pos] = src1[i];
    } else if (i < 2 * E) {
        int e = i - E;
        int d = dst2[e];
        int pos = g_rowptr[1][d] + atomicAdd(&g_fill[1][d], 1);
        g_esrc[1][pos] = src2[e];
    }
}

// ---------------- aggregation: warp per node, lane = 4 columns ----------------
// h = (1-ALPHA) * norm[n] * sum_e feat_in[src_e]*norm[src_e]  +  ALPHA * feat0[n]
__global__ void k_agg(int g, const float* __restrict__ feat_ext,
                      const float* __restrict__ feat0, int n) {
    int warp = (blockIdx.x * blockDim.x + threadIdx.x) >> 5;
    if (warp >= n) return;
    int lane = threadIdx.x & 31;

    const float* __restrict__ fin = feat_ext ? feat_ext : g_feat[g];
    const int*   __restrict__ rp  = g_rowptr[g];
    const int*   __restrict__ es  = g_esrc[g];
    const float* __restrict__ nrm = g_norm[g];

    int s = rp[warp], e = rp[warp + 1];
    float ax = 0.f, ay = 0.f, az = 0.f, aw = 0.f;

    int i = s;
    // unroll by 4 edges for MLP (hide L2 gather latency)
    for (; i + 4 <= e; i += 4) {
        int s0 = __ldg(&es[i + 0]), s1 = __ldg(&es[i + 1]);
        int s2 = __ldg(&es[i + 2]), s3 = __ldg(&es[i + 3]);
        float n0 = __ldg(&nrm[s0]), n1 = __ldg(&nrm[s1]);
        float n2 = __ldg(&nrm[s2]), n3 = __ldg(&nrm[s3]);
        float4 v0 = __ldg((const float4*)&fin[(size_t)s0 * D + lane * 4]);
        float4 v1 = __ldg((const float4*)&fin[(size_t)s1 * D + lane * 4]);
        float4 v2 = __ldg((const float4*)&fin[(size_t)s2 * D + lane * 4]);
        float4 v3 = __ldg((const float4*)&fin[(size_t)s3 * D + lane * 4]);
        ax = fmaf(v0.x, n0, ax); ay = fmaf(v0.y, n0, ay); az = fmaf(v0.z, n0, az); aw = fmaf(v0.w, n0, aw);
        ax = fmaf(v1.x, n1, ax); ay = fmaf(v1.y, n1, ay); az = fmaf(v1.z, n1, az); aw = fmaf(v1.w, n1, aw);
        ax = fmaf(v2.x, n2, ax); ay = fmaf(v2.y, n2, ay); az = fmaf(v2.z, n2, az); aw = fmaf(v2.w, n2, aw);
        ax = fmaf(v3.x, n3, ax); ay = fmaf(v3.y, n3, ay); az = fmaf(v3.z, n3, az); aw = fmaf(v3.w, n3, aw);
    }
    for (; i < e; i++) {
        int sv = __ldg(&es[i]);
        float nv = __ldg(&nrm[sv]);
        float4 v = __ldg((const float4*)&fin[(size_t)sv * D + lane * 4]);
        ax = fmaf(v.x, nv, ax); ay = fmaf(v.y, nv, ay);
        az = fmaf(v.z, nv, az); aw = fmaf(v.w, nv, aw);
    }

    float nd = nrm[warp] * 0.9f;  // (1 - ALPHA) folded in
    float4 f0 = __ldg((const float4*)&feat0[(size_t)warp * D + lane * 4]);
    float4 o;
    o.x = fmaf(ax, nd, 0.1f * f0.x);
    o.y = fmaf(ay, nd, 0.1f * f0.y);
    o.z = fmaf(az, nd, 0.1f * f0.z);
    o.w = fmaf(aw, nd, 0.1f * f0.w);
    *(float4*)&g_h[g][(size_t)warp * D + lane * 4] = o;
}

// ---------------- GEMM + GCNII epilogue ----------------
// out[n,j] = relu( (1-beta)*h[n,j] + beta*sum_k h[n,k]*W[k,j] + bias[j] )
// 256 threads, 64 rows/block, thread = (row, 32-col chunk). W from L1, h tile in padded smem.
#define HS_STRIDE 132
__global__ void __launch_bounds__(256) k_gemm(int g, const float* __restrict__ W,
                                              const float* __restrict__ bias, float beta,
                                              float* __restrict__ out_ext, int n) {
    __shared__ float hs[64 * HS_STRIDE];
    int row0 = blockIdx.x * 64;
    int tid = threadIdx.x;
    const float* __restrict__ hin = g_h[g];

    // stage h tile [64][128] into smem (padded stride for conflict-free row reads)
    for (int i = tid; i < 64 * 32; i += 256) {
        int r = i >> 5, c4 = i & 31;
        int grow = row0 + r;
        float4 v = (grow < n) ? __ldg((const float4*)&hin[(size_t)grow * D + c4 * 4])
                              : make_float4(0.f, 0.f, 0.f, 0.f);
        *(float4*)&hs[r * HS_STRIDE + c4 * 4] = v;
    }
    __syncthreads();

    int lr = tid >> 2;            // local row 0..63
    int cb = (tid & 3) * 32;      // column chunk base
    float acc[32];
#pragma unroll
    for (int q = 0; q < 32; q++) acc[q] = 0.f;

    const float* hrow = &hs[lr * HS_STRIDE];
#pragma unroll 8
    for (int k = 0; k < D; k++) {
        float hk = hrow[k];
        const float4* wp = (const float4*)&W[k * D + cb];
#pragma unroll
        for (int q = 0; q < 8; q++) {
            float4 w = __ldg(&wp[q]);
            acc[q * 4 + 0] = fmaf(hk, w.x, acc[q * 4 + 0]);
            acc[q * 4 + 1] = fmaf(hk, w.y, acc[q * 4 + 1]);
            acc[q * 4 + 2] = fmaf(hk, w.z, acc[q * 4 + 2]);
            acc[q * 4 + 3] = fmaf(hk, w.w, acc[q * 4 + 3]);
        }
    }

    int grow = row0 + lr;
    if (grow < n) {
        float* __restrict__ outp = out_ext ? out_ext : g_feat[g];
        float omb = 1.0f - beta;
        float4 b0 = __ldg((const float4*)&bias[cb + 0]);
        float4 b1 = __ldg((const float4*)&bias[cb + 4]);
        float4 b2 = __ldg((const float4*)&bias[cb + 8]);
        float4 b3 = __ldg((const float4*)&bias[cb + 12]);
        float4 b4v = __ldg((const float4*)&bias[cb + 16]);
        float4 b5 = __ldg((const float4*)&bias[cb + 20]);
        float4 b6 = __ldg((const float4*)&bias[cb + 24]);
        float4 b7 = __ldg((const float4*)&bias[cb + 28]);
        float4 bb[8] = {b0, b1, b2, b3, b4v, b5, b6, b7};
#pragma unroll
        for (int q = 0; q < 8; q++) {
            int j = cb + q * 4;
            float4 o;
            o.x = fmaxf(fmaf(beta, acc[q * 4 + 0], omb * hrow[j + 0]) + bb[q].x, 0.f);
            o.y = fmaxf(fmaf(beta, acc[q * 4 + 1], omb * hrow[j + 1]) + bb[q].y, 0.f);
            o.z = fmaxf(fmaf(beta, acc[q * 4 + 2], omb * hrow[j + 2]) + bb[q].z, 0.f);
            o.w = fmaxf(fmaf(beta, acc[q * 4 + 3], omb * hrow[j + 3]) + bb[q].w, 0.f);
            *(float4*)&outp[(size_t)grow * D + j] = o;
        }
    }
}

// ---------------- standardization ----------------
__global__ void k_stats(const float* __restrict__ x, int g, int n) {
    int col = threadIdx.x;  // 128 threads
    int rows_per_block = (n + gridDim.x - 1) / gridDim.x;
    int r0 = blockIdx.x * rows_per_block;
    int r1 = min(r0 + rows_per_block, n);
    double ds = 0.0, ds2 = 0.0;
    for (int r = r0; r < r1; r++) {
        float v = x[(size_t)r * D + col];
        ds += (double)v;
        ds2 += (double)v * (double)v;
    }
    atomicAdd(&g_sum[g][col], ds);
    atomicAdd(&g_sumsq[g][col], ds2);
}

__global__ void k_finalize(int n) {
    int i = threadIdx.x;  // 256 threads = 2 graphs x 128 cols
    int g = i >> 7, c = i & 127;
    double s = g_sum[g][c], s2 = g_sumsq[g][c];
    double mean = s / n;
    double var = (s2 - s * s / (double)n) / (double)(n - 1);
    float sd = (float)sqrt(var > 0.0 ? var : 0.0);
    g_mean[g][c] = (float)mean;
    g_rstd[g][c] = 1.0f / fmaxf(sd, 1e-12f);
}

__global__ void k_norm(float* __restrict__ out, int n) {
    int i = blockIdx.x * blockDim.x + threadIdx.x;
    int total = 2 * n * D;
    if (i >= total) return;
    int g = (i >= n * D) ? 1 : 0;
    int c = i & 127;
    out[i] = (out[i] - g_mean[g][c]) * g_rstd[g][c];
}

// ---------------- launch ----------------
extern "C" void kernel_launch(void* const* d_in, const int* in_sizes, int n_in,
                              void* d_out, int out_size) {
    const float* feat1   = (const float*)d_in[0];
    const float* feat2   = (const float*)d_in[1];
    const int*   src1    = (const int*)d_in[2];
    const int*   dst1    = (const int*)d_in[3];
    const int*   src2    = (const int*)d_in[4];
    const int*   dst2    = (const int*)d_in[5];
    const float* weights = (const float*)d_in[6];
    const float* biases  = (const float*)d_in[7];
    float* out = (float*)d_out;

    int n = in_sizes[0] / D;
    int E = in_sizes[2];
    int L = in_sizes[6] / (D * D);

    k_init<<<(n + 255) / 256, 256>>>(n);
    k_hist<<<(2 * E + 255) / 256, 256>>>(dst1, dst2, E);
    k_scan<<<2, 1024>>>(n);
    k_fill<<<(2 * E + 255) / 256, 256>>>(src1, dst1, src2, dst2, E);

    const float* f0[2] = {feat1, feat2};
    for (int g = 0; g < 2; g++) {
        for (int l = 0; l < L; l++) {
            const float* fin = (l == 0) ? f0[g] : nullptr;  // null -> g_feat[g]
            k_agg<<<(n * 32 + 255) / 256, 256>>>(g, fin, f0[g], n);

            float beta = (float)log(1.0 / (double)(l + 1) + 1.0);
            float* gout = (l == L - 1) ? (out + (size_t)g * n * D) : nullptr;  // null -> g_feat[g]
            k_gemm<<<(n + 63) / 64, 256>>>(g, weights + (size_t)l * D * D,
                                           biases + (size_t)l * D, beta, gout, n);
        }
    }

    k_stats<<<512, 128>>>(out, 0, n);
    k_stats<<<512, 128>>>(out + (size_t)n * D, 1, n);
    k_finalize<<<1, 256>>>(n);
    k_norm<<<(2 * n * D + 255) / 256, 256>>>(out, n);
}

// round 4
// speedup vs baseline: 3.7079x; 3.7079x over previous
#include <cuda_runtime.h>
#include <math.h>

#define NN   100000
#define D    128
#define EMAX 1600000

// ---------------- scratch (device globals; no allocation allowed) ----------------
__device__ int    g_cnt[2][NN];        // in-degree counts
__device__ int    g_fill[2][NN];       // CSR fill cursors
__device__ int    g_rowptr[2][NN + 1]; // CSR row pointers (by dst)
__device__ int    g_esrc[2][EMAX];     // CSR: src node per edge slot
__device__ float  g_norm[2][NN];       // D^-1/2 normalization
__device__ float  g_feat[2][NN * D];   // current layer features
__device__ float  g_h[2][NN * D];      // post-aggregation residual features
__device__ double g_sum[2][D];
__device__ double g_sumsq[2][D];
__device__ float  g_mean[2][D];
__device__ float  g_rstd[2][D];

// ---------------- prep kernels ----------------
__global__ void k_init(int n) {
    int i = blockIdx.x * blockDim.x + threadIdx.x;
    if (i < n) {
        g_cnt[0][i] = 0; g_cnt[1][i] = 0;
        g_fill[0][i] = 0; g_fill[1][i] = 0;
    }
    if (i < D) {
        g_sum[0][i] = 0.0; g_sum[1][i] = 0.0;
        g_sumsq[0][i] = 0.0; g_sumsq[1][i] = 0.0;
    }
}

__global__ void k_hist(const int* __restrict__ dst1, const int* __restrict__ dst2, int E) {
    int i = blockIdx.x * blockDim.x + threadIdx.x;
    if (i < E) {
        atomicAdd(&g_cnt[0][dst1[i]], 1);
    } else if (i < 2 * E) {
        atomicAdd(&g_cnt[1][dst2[i - E]], 1);
    }
}

// one block per graph; warp-shuffle scan per 1024-tile; also emits norm
__global__ void k_scan(int n) {
    int g = blockIdx.x;
    __shared__ int warp_tot[32];
    __shared__ int s_off;
    int lane = threadIdx.x & 31;
    int wid = threadIdx.x >> 5;
    if (threadIdx.x == 0) s_off = 0;
    __syncthreads();
    for (int base = 0; base < n; base += 1024) {
        int i = base + threadIdx.x;
        int v = (i < n) ? g_cnt[g][i] : 0;
        if (i < n) g_norm[g][i] = rsqrtf((float)max(v, 1));
        // inclusive warp scan
        int x = v;
#pragma unroll
        for (int ofs = 1; ofs < 32; ofs <<= 1) {
            int t = __shfl_up_sync(0xFFFFFFFFu, x, ofs);
            if (lane >= ofs) x += t;
        }
        if (lane == 31) warp_tot[wid] = x;
        __syncthreads();
        // warp 0 scans the 32 warp totals (exclusive)
        if (wid == 0) {
            int wt = warp_tot[lane];
            int y = wt;
#pragma unroll
            for (int ofs = 1; ofs < 32; ofs <<= 1) {
                int t = __shfl_up_sync(0xFFFFFFFFu, y, ofs);
                if (lane >= ofs) y += t;
            }
            warp_tot[lane] = y - wt;  // exclusive prefix of warp totals
        }
        __syncthreads();
        int excl = s_off + warp_tot[wid] + (x - v);
        if (i < n) g_rowptr[g][i] = excl;
        __syncthreads();
        if (threadIdx.x == 1023) s_off = excl + v;
        __syncthreads();
    }
    if (threadIdx.x == 0) g_rowptr[g][n] = s_off;
}

__global__ void k_fill(const int* __restrict__ src1, const int* __restrict__ dst1,
                       const int* __restrict__ src2, const int* __restrict__ dst2, int E) {
    int i = blockIdx.x * blockDim.x + threadIdx.x;
    if (i < E) {
        int d = dst1[i];
        int pos = g_rowptr[0][d] + atomicAdd(&g_fill[0][d], 1);
        g_esrc[0][pos] = src1[i];
    } else if (i < 2 * E) {
        int e = i - E;
        int d = dst2[e];
        int pos = g_rowptr[1][d] + atomicAdd(&g_fill[1][d], 1);
        g_esrc[1][pos] = src2[e];
    }
}

// ---------------- aggregation: warp per node, lane = 4 columns ----------------
// h = (1-ALPHA) * norm[n] * sum_e feat_in[src_e]*norm[src_e]  +  ALPHA * feat0[n]
__global__ void k_agg(int g, const float* __restrict__ feat_ext,
                      const float* __restrict__ feat0, int n) {
    int warp = (blockIdx.x * blockDim.x + threadIdx.x) >> 5;
    if (warp >= n) return;
    int lane = threadIdx.x & 31;

    const float* __restrict__ fin = feat_ext ? feat_ext : g_feat[g];
    const int*   __restrict__ rp  = g_rowptr[g];
    const int*   __restrict__ es  = g_esrc[g];
    const float* __restrict__ nrm = g_norm[g];

    int s = rp[warp], e = rp[warp + 1];
    float ax = 0.f, ay = 0.f, az = 0.f, aw = 0.f;

    int i = s;
    // unroll by 4 edges for MLP (hide L2 gather latency)
    for (; i + 4 <= e; i += 4) {
        int s0 = __ldg(&es[i + 0]), s1 = __ldg(&es[i + 1]);
        int s2 = __ldg(&es[i + 2]), s3 = __ldg(&es[i + 3]);
        float n0 = __ldg(&nrm[s0]), n1 = __ldg(&nrm[s1]);
        float n2 = __ldg(&nrm[s2]), n3 = __ldg(&nrm[s3]);
        float4 v0 = __ldg((const float4*)&fin[(size_t)s0 * D + lane * 4]);
        float4 v1 = __ldg((const float4*)&fin[(size_t)s1 * D + lane * 4]);
        float4 v2 = __ldg((const float4*)&fin[(size_t)s2 * D + lane * 4]);
        float4 v3 = __ldg((const float4*)&fin[(size_t)s3 * D + lane * 4]);
        ax = fmaf(v0.x, n0, ax); ay = fmaf(v0.y, n0, ay); az = fmaf(v0.z, n0, az); aw = fmaf(v0.w, n0, aw);
        ax = fmaf(v1.x, n1, ax); ay = fmaf(v1.y, n1, ay); az = fmaf(v1.z, n1, az); aw = fmaf(v1.w, n1, aw);
        ax = fmaf(v2.x, n2, ax); ay = fmaf(v2.y, n2, ay); az = fmaf(v2.z, n2, az); aw = fmaf(v2.w, n2, aw);
        ax = fmaf(v3.x, n3, ax); ay = fmaf(v3.y, n3, ay); az = fmaf(v3.z, n3, az); aw = fmaf(v3.w, n3, aw);
    }
    for (; i < e; i++) {
        int sv = __ldg(&es[i]);
        float nv = __ldg(&nrm[sv]);
        float4 v = __ldg((const float4*)&fin[(size_t)sv * D + lane * 4]);
        ax = fmaf(v.x, nv, ax); ay = fmaf(v.y, nv, ay);
        az = fmaf(v.z, nv, az); aw = fmaf(v.w, nv, aw);
    }

    float nd = nrm[warp] * 0.9f;  // (1 - ALPHA) folded in
    float4 f0 = __ldg((const float4*)&feat0[(size_t)warp * D + lane * 4]);
    float4 o;
    o.x = fmaf(ax, nd, 0.1f * f0.x);
    o.y = fmaf(ay, nd, 0.1f * f0.y);
    o.z = fmaf(az, nd, 0.1f * f0.z);
    o.w = fmaf(aw, nd, 0.1f * f0.w);
    *(float4*)&g_h[g][(size_t)warp * D + lane * 4] = o;
}

// ---------------- GEMM + GCNII epilogue ----------------
// out[n,j] = relu( (1-beta)*h[n,j] + beta*sum_k h[n,k]*W[k,j] + bias[j] )
// Tiled SGEMM: full W (64KB) + 64-row h tile in DYNAMIC smem (static limit is 48KB).
// 256 threads, thread = 4 rows x 8 cols micro-tile. 2 blocks/SM.
#define RB 64
#define HS 132
#define GEMM_SMEM_BYTES ((RB * HS + 128 * 128) * (int)sizeof(float))  // 99,328 B
__global__ void __launch_bounds__(256, 2) k_gemm(int g, const float* __restrict__ W,
                                                 const float* __restrict__ bias, float beta,
                                                 float* __restrict__ out_ext, int n) {
    extern __shared__ float smem_dyn[];
    float* hs = smem_dyn;              // RB * HS  (33.8 KB, padded stride)
    float* ws = smem_dyn + RB * HS;    // 128*128  (64 KB)
    int row0 = blockIdx.x * RB;
    int tid = threadIdx.x;
    const float* __restrict__ hin = g_h[g];

    // stage full W into smem (coalesced float4)
    const float4* __restrict__ W4 = (const float4*)W;
#pragma unroll
    for (int i = 0; i < 16; i++) {
        int idx = tid + i * 256;           // 4096 float4 total
        *(float4*)&ws[idx * 4] = __ldg(&W4[idx]);
    }
    // stage h tile [64][128] (padded stride)
#pragma unroll
    for (int i = 0; i < 8; i++) {
        int idx = tid + i * 256;           // 2048 float4 total
        int r = idx >> 5, c4 = idx & 31;
        int grow = row0 + r;
        float4 v = (grow < n) ? __ldg((const float4*)&hin[(size_t)grow * D + c4 * 4])
                              : make_float4(0.f, 0.f, 0.f, 0.f);
        *(float4*)&hs[r * HS + c4 * 4] = v;
    }
    __syncthreads();

    int tx = tid & 15, ty = tid >> 4;
    int cb = tx * 8;       // 8-column chunk
    int rb = ty * 4;       // 4-row chunk

    float acc[4][8];
#pragma unroll
    for (int r = 0; r < 4; r++)
#pragma unroll
        for (int c = 0; c < 8; c++) acc[r][c] = 0.f;

    const float* h0p = &hs[(rb + 0) * HS];
    const float* h1p = &hs[(rb + 1) * HS];
    const float* h2p = &hs[(rb + 2) * HS];
    const float* h3p = &hs[(rb + 3) * HS];

#pragma unroll 2
    for (int k = 0; k < D; k++) {
        float4 wa = *(const float4*)&ws[k * 128 + cb];
        float4 wb = *(const float4*)&ws[k * 128 + cb + 4];
        float h0 = h0p[k], h1 = h1p[k], h2 = h2p[k], h3 = h3p[k];
        acc[0][0] = fmaf(h0, wa.x, acc[0][0]); acc[0][1] = fmaf(h0, wa.y, acc[0][1]);
        acc[0][2] = fmaf(h0, wa.z, acc[0][2]); acc[0][3] = fmaf(h0, wa.w, acc[0][3]);
        acc[0][4] = fmaf(h0, wb.x, acc[0][4]); acc[0][5] = fmaf(h0, wb.y, acc[0][5]);
        acc[0][6] = fmaf(h0, wb.z, acc[0][6]); acc[0][7] = fmaf(h0, wb.w, acc[0][7]);
        acc[1][0] = fmaf(h1, wa.x, acc[1][0]); acc[1][1] = fmaf(h1, wa.y, acc[1][1]);
        acc[1][2] = fmaf(h1, wa.z, acc[1][2]); acc[1][3] = fmaf(h1, wa.w, acc[1][3]);
        acc[1][4] = fmaf(h1, wb.x, acc[1][4]); acc[1][5] = fmaf(h1, wb.y, acc[1][5]);
        acc[1][6] = fmaf(h1, wb.z, acc[1][6]); acc[1][7] = fmaf(h1, wb.w, acc[1][7]);
        acc[2][0] = fmaf(h2, wa.x, acc[2][0]); acc[2][1] = fmaf(h2, wa.y, acc[2][1]);
        acc[2][2] = fmaf(h2, wa.z, acc[2][2]); acc[2][3] = fmaf(h2, wa.w, acc[2][3]);
        acc[2][4] = fmaf(h2, wb.x, acc[2][4]); acc[2][5] = fmaf(h2, wb.y, acc[2][5]);
        acc[2][6] = fmaf(h2, wb.z, acc[2][6]); acc[2][7] = fmaf(h2, wb.w, acc[2][7]);
        acc[3][0] = fmaf(h3, wa.x, acc[3][0]); acc[3][1] = fmaf(h3, wa.y, acc[3][1]);
        acc[3][2] = fmaf(h3, wa.z, acc[3][2]); acc[3][3] = fmaf(h3, wa.w, acc[3][3]);
        acc[3][4] = fmaf(h3, wb.x, acc[3][4]); acc[3][5] = fmaf(h3, wb.y, acc[3][5]);
        acc[3][6] = fmaf(h3, wb.z, acc[3][6]); acc[3][7] = fmaf(h3, wb.w, acc[3][7]);
    }

    float omb = 1.0f - beta;
    float* __restrict__ outp = out_ext ? out_ext : g_feat[g];
    float4 ba = __ldg((const float4*)&bias[cb]);
    float4 bb4 = __ldg((const float4*)&bias[cb + 4]);
#pragma unroll
    for (int r = 0; r < 4; r++) {
        int grow = row0 + rb + r;
        if (grow < n) {
            const float* hr = &hs[(rb + r) * HS + cb];
            float4 o0, o1;
            o0.x = fmaxf(fmaf(beta, acc[r][0], omb * hr[0]) + ba.x, 0.f);
            o0.y = fmaxf(fmaf(beta, acc[r][1], omb * hr[1]) + ba.y, 0.f);
            o0.z = fmaxf(fmaf(beta, acc[r][2], omb * hr[2]) + ba.z, 0.f);
            o0.w = fmaxf(fmaf(beta, acc[r][3], omb * hr[3]) + ba.w, 0.f);
            o1.x = fmaxf(fmaf(beta, acc[r][4], omb * hr[4]) + bb4.x, 0.f);
            o1.y = fmaxf(fmaf(beta, acc[r][5], omb * hr[5]) + bb4.y, 0.f);
            o1.z = fmaxf(fmaf(beta, acc[r][6], omb * hr[6]) + bb4.z, 0.f);
            o1.w = fmaxf(fmaf(beta, acc[r][7], omb * hr[7]) + bb4.w, 0.f);
            *(float4*)&outp[(size_t)grow * D + cb]     = o0;
            *(float4*)&outp[(size_t)grow * D + cb + 4] = o1;
        }
    }
}

// ---------------- standardization ----------------
__global__ void k_stats(const float* __restrict__ x, int g, int n) {
    int col = threadIdx.x;  // 128 threads
    int rows_per_block = (n + gridDim.x - 1) / gridDim.x;
    int r0 = blockIdx.x * rows_per_block;
    int r1 = min(r0 + rows_per_block, n);
    double ds = 0.0, ds2 = 0.0;
    for (int r = r0; r < r1; r++) {
        float v = x[(size_t)r * D + col];
        ds += (double)v;
        ds2 += (double)v * (double)v;
    }
    atomicAdd(&g_sum[g][col], ds);
    atomicAdd(&g_sumsq[g][col], ds2);
}

__global__ void k_finalize(int n) {
    int i = threadIdx.x;  // 256 threads = 2 graphs x 128 cols
    int g = i >> 7, c = i & 127;
    double s = g_sum[g][c], s2 = g_sumsq[g][c];
    double mean = s / n;
    double var = (s2 - s * s / (double)n) / (double)(n - 1);
    float sd = (float)sqrt(var > 0.0 ? var : 0.0);
    g_mean[g][c] = (float)mean;
    g_rstd[g][c] = 1.0f / fmaxf(sd, 1e-12f);
}

__global__ void k_norm(float* __restrict__ out, int n) {
    int i = blockIdx.x * blockDim.x + threadIdx.x;
    int total = 2 * n * D;
    if (i >= total) return;
    int g = (i >= n * D) ? 1 : 0;
    int c = i & 127;
    out[i] = (out[i] - g_mean[g][c]) * g_rstd[g][c];
}

// ---------------- launch ----------------
extern "C" void kernel_launch(void* const* d_in, const int* in_sizes, int n_in,
                              void* d_out, int out_size) {
    const float* feat1   = (const float*)d_in[0];
    const float* feat2   = (const float*)d_in[1];
    const int*   src1    = (const int*)d_in[2];
    const int*   dst1    = (const int*)d_in[3];
    const int*   src2    = (const int*)d_in[4];
    const int*   dst2    = (const int*)d_in[5];
    const float* weights = (const float*)d_in[6];
    const float* biases  = (const float*)d_in[7];
    float* out = (float*)d_out;

    int n = in_sizes[0] / D;
    int E = in_sizes[2];
    int L = in_sizes[6] / (D * D);

    // opt in to >48KB dynamic smem for the GEMM (non-stream call; capture-safe)
    cudaFuncSetAttribute(k_gemm, cudaFuncAttributeMaxDynamicSharedMemorySize,
                         GEMM_SMEM_BYTES);

    k_init<<<(n + 255) / 256, 256>>>(n);
    k_hist<<<(2 * E + 255) / 256, 256>>>(dst1, dst2, E);
    k_scan<<<2, 1024>>>(n);
    k_fill<<<(2 * E + 255) / 256, 256>>>(src1, dst1, src2, dst2, E);

    const float* f0[2] = {feat1, feat2};
    for (int g = 0; g < 2; g++) {
        for (int l = 0; l < L; l++) {
            const float* fin = (l == 0) ? f0[g] : nullptr;  // null -> g_feat[g]
            k_agg<<<(n * 32 + 255) / 256, 256>>>(g, fin, f0[g], n);

            float beta = (float)log(1.0 / (double)(l + 1) + 1.0);
            float* gout = (l == L - 1) ? (out + (size_t)g * n * D) : nullptr;  // null -> g_feat[g]
            k_gemm<<<(n + RB - 1) / RB, 256, GEMM_SMEM_BYTES>>>(
                g, weights + (size_t)l * D * D, biases + (size_t)l * D, beta, gout, n);
        }
    }

    k_stats<<<512, 128>>>(out, 0, n);
    k_stats<<<512, 128>>>(out + (size_t)n * D, 1, n);
    k_finalize<<<1, 256>>>(n);
    k_norm<<<(2 * n * D + 255) / 256, 256>>>(out, n);
}

// round 5
// speedup vs baseline: 3.7681x; 1.0162x over previous
#include <cuda_runtime.h>
#include <math.h>

#define NN   100000
#define D    128
#define EMAX 1600000

// ---------------- scratch (device globals; no allocation allowed) ----------------
__device__ int    g_cnt[2][NN];        // in-degree counts
__device__ int    g_fill[2][NN];       // CSR fill cursors
__device__ int    g_rowptr[2][NN + 1]; // CSR row pointers (by dst)
__device__ int    g_esrc[2][EMAX];     // CSR: src node per edge slot
__device__ float  g_norm[2][NN];       // D^-1/2 normalization
__device__ float  g_feat[2][NN * D];   // current layer features
__device__ float  g_h[2][NN * D];      // post-aggregation residual features
__device__ double g_sum[2][D];
__device__ double g_sumsq[2][D];
__device__ float  g_mean[2][D];
__device__ float  g_rstd[2][D];

// packed fp32x2 helpers (exact fp32 per lane; sm_100a packed-math)
__device__ __forceinline__ unsigned long long f32x2_dup(float a) {
    unsigned long long r;
    unsigned int ai = __float_as_uint(a);
    asm("mov.b64 %0, {%1, %1};" : "=l"(r) : "r"(ai));
    return r;
}
__device__ __forceinline__ unsigned long long f32x2_fma(unsigned long long a,
                                                        unsigned long long b,
                                                        unsigned long long c) {
    unsigned long long r;
    asm("fma.rn.f32x2 %0, %1, %2, %3;" : "=l"(r) : "l"(a), "l"(b), "l"(c));
    return r;
}
__device__ __forceinline__ void f32x2_unpack(unsigned long long v, float& lo, float& hi) {
    unsigned int l, h;
    asm("mov.b64 {%0, %1}, %2;" : "=r"(l), "=r"(h) : "l"(v));
    lo = __uint_as_float(l);
    hi = __uint_as_float(h);
}

// ---------------- prep kernels ----------------
__global__ void k_init(int n) {
    int i = blockIdx.x * blockDim.x + threadIdx.x;
    if (i < n) {
        g_cnt[0][i] = 0; g_cnt[1][i] = 0;
        g_fill[0][i] = 0; g_fill[1][i] = 0;
    }
    if (i < D) {
        g_sum[0][i] = 0.0; g_sum[1][i] = 0.0;
        g_sumsq[0][i] = 0.0; g_sumsq[1][i] = 0.0;
    }
}

__global__ void k_hist(const int* __restrict__ dst1, const int* __restrict__ dst2, int E) {
    int i = blockIdx.x * blockDim.x + threadIdx.x;
    if (i < E) {
        atomicAdd(&g_cnt[0][dst1[i]], 1);
    } else if (i < 2 * E) {
        atomicAdd(&g_cnt[1][dst2[i - E]], 1);
    }
}

// one block per graph; warp-shuffle scan per 1024-tile; also emits norm
__global__ void k_scan(int n) {
    int g = blockIdx.x;
    __shared__ int warp_tot[32];
    __shared__ int s_off;
    int lane = threadIdx.x & 31;
    int wid = threadIdx.x >> 5;
    if (threadIdx.x == 0) s_off = 0;
    __syncthreads();
    for (int base = 0; base < n; base += 1024) {
        int i = base + threadIdx.x;
        int v = (i < n) ? g_cnt[g][i] : 0;
        if (i < n) g_norm[g][i] = rsqrtf((float)max(v, 1));
        int x = v;
#pragma unroll
        for (int ofs = 1; ofs < 32; ofs <<= 1) {
            int t = __shfl_up_sync(0xFFFFFFFFu, x, ofs);
            if (lane >= ofs) x += t;
        }
        if (lane == 31) warp_tot[wid] = x;
        __syncthreads();
        if (wid == 0) {
            int wt = warp_tot[lane];
            int y = wt;
#pragma unroll
            for (int ofs = 1; ofs < 32; ofs <<= 1) {
                int t = __shfl_up_sync(0xFFFFFFFFu, y, ofs);
                if (lane >= ofs) y += t;
            }
            warp_tot[lane] = y - wt;  // exclusive prefix of warp totals
        }
        __syncthreads();
        int excl = s_off + warp_tot[wid] + (x - v);
        if (i < n) g_rowptr[g][i] = excl;
        __syncthreads();
        if (threadIdx.x == 1023) s_off = excl + v;
        __syncthreads();
    }
    if (threadIdx.x == 0) g_rowptr[g][n] = s_off;
}

__global__ void k_fill(const int* __restrict__ src1, const int* __restrict__ dst1,
                       const int* __restrict__ src2, const int* __restrict__ dst2, int E) {
    int i = blockIdx.x * blockDim.x + threadIdx.x;
    if (i < E) {
        int d = dst1[i];
        int pos = g_rowptr[0][d] + atomicAdd(&g_fill[0][d], 1);
        g_esrc[0][pos] = src1[i];
    } else if (i < 2 * E) {
        int e = i - E;
        int d = dst2[e];
        int pos = g_rowptr[1][d] + atomicAdd(&g_fill[1][d], 1);
        g_esrc[1][pos] = src2[e];
    }
}

// ---------------- aggregation: warp per node, both graphs in one launch ----------------
// h = (1-ALPHA) * norm[n] * sum_e feat_in[src_e]*norm[src_e]  +  ALPHA * feat0[n]
__global__ void k_agg(const float* __restrict__ ext1, const float* __restrict__ ext2,
                      const float* __restrict__ feat01, const float* __restrict__ feat02,
                      int n) {
    int gw = (blockIdx.x * blockDim.x + threadIdx.x) >> 5;
    if (gw >= 2 * n) return;
    int g = (gw >= n) ? 1 : 0;
    int node = gw - g * n;
    int lane = threadIdx.x & 31;

    const float* __restrict__ fin = ext1 ? (g ? ext2 : ext1) : g_feat[g];
    const float* __restrict__ feat0 = g ? feat02 : feat01;
    const int*   __restrict__ rp  = g_rowptr[g];
    const int*   __restrict__ es  = g_esrc[g];
    const float* __restrict__ nrm = g_norm[g];

    int s = rp[node], e = rp[node + 1];
    float ax = 0.f, ay = 0.f, az = 0.f, aw = 0.f;

    int i = s;
    for (; i + 4 <= e; i += 4) {
        int s0 = __ldg(&es[i + 0]), s1 = __ldg(&es[i + 1]);
        int s2 = __ldg(&es[i + 2]), s3 = __ldg(&es[i + 3]);
        float n0 = __ldg(&nrm[s0]), n1 = __ldg(&nrm[s1]);
        float n2 = __ldg(&nrm[s2]), n3 = __ldg(&nrm[s3]);
        float4 v0 = __ldg((const float4*)&fin[(size_t)s0 * D + lane * 4]);
        float4 v1 = __ldg((const float4*)&fin[(size_t)s1 * D + lane * 4]);
        float4 v2 = __ldg((const float4*)&fin[(size_t)s2 * D + lane * 4]);
        float4 v3 = __ldg((const float4*)&fin[(size_t)s3 * D + lane * 4]);
        ax = fmaf(v0.x, n0, ax); ay = fmaf(v0.y, n0, ay); az = fmaf(v0.z, n0, az); aw = fmaf(v0.w, n0, aw);
        ax = fmaf(v1.x, n1, ax); ay = fmaf(v1.y, n1, ay); az = fmaf(v1.z, n1, az); aw = fmaf(v1.w, n1, aw);
        ax = fmaf(v2.x, n2, ax); ay = fmaf(v2.y, n2, ay); az = fmaf(v2.z, n2, az); aw = fmaf(v2.w, n2, aw);
        ax = fmaf(v3.x, n3, ax); ay = fmaf(v3.y, n3, ay); az = fmaf(v3.z, n3, az); aw = fmaf(v3.w, n3, aw);
    }
    for (; i < e; i++) {
        int sv = __ldg(&es[i]);
        float nv = __ldg(&nrm[sv]);
        float4 v = __ldg((const float4*)&fin[(size_t)sv * D + lane * 4]);
        ax = fmaf(v.x, nv, ax); ay = fmaf(v.y, nv, ay);
        az = fmaf(v.z, nv, az); aw = fmaf(v.w, nv, aw);
    }

    float nd = nrm[node] * 0.9f;  // (1 - ALPHA) folded in
    float4 f0 = __ldg((const float4*)&feat0[(size_t)node * D + lane * 4]);
    float4 o;
    o.x = fmaf(ax, nd, 0.1f * f0.x);
    o.y = fmaf(ay, nd, 0.1f * f0.y);
    o.z = fmaf(az, nd, 0.1f * f0.z);
    o.w = fmaf(aw, nd, 0.1f * f0.w);
    *(float4*)&g_h[g][(size_t)node * D + lane * 4] = o;
}

// ---------------- GEMM + GCNII epilogue (packed f32x2 FMA, both graphs) ----------------
// out[n,j] = relu( (1-beta)*h[n,j] + beta*sum_k h[n,k]*W[k,j] + bias[j] )
// Full W (64KB) + 64-row h tile in dynamic smem. 256 threads,
// thread = 4 rows x 8 cols (as 4 col-pairs). fma.rn.f32x2: 2 exact fp32 FMA/instr.
#define RB 64
#define HS 132
#define GEMM_SMEM_BYTES ((RB * HS + 128 * 128) * (int)sizeof(float))  // 99,328 B
__global__ void __launch_bounds__(256, 2) k_gemm(const float* __restrict__ W,
                                                 const float* __restrict__ bias, float beta,
                                                 float* __restrict__ out_base, int n, int bpg) {
    extern __shared__ float smem_dyn[];
    float* hs = smem_dyn;              // RB * HS
    float* ws = smem_dyn + RB * HS;    // 128*128
    int g = (blockIdx.x >= bpg) ? 1 : 0;
    int row0 = (blockIdx.x - g * bpg) * RB;
    int tid = threadIdx.x;
    const float* __restrict__ hin = g_h[g];

    // stage full W into smem (coalesced float4)
    const float4* __restrict__ W4 = (const float4*)W;
#pragma unroll
    for (int i = 0; i < 16; i++) {
        int idx = tid + i * 256;
        *(float4*)&ws[idx * 4] = __ldg(&W4[idx]);
    }
    // stage h tile [64][128] (padded stride)
#pragma unroll
    for (int i = 0; i < 8; i++) {
        int idx = tid + i * 256;
        int r = idx >> 5, c4 = idx & 31;
        int grow = row0 + r;
        float4 v = (grow < n) ? __ldg((const float4*)&hin[(size_t)grow * D + c4 * 4])
                              : make_float4(0.f, 0.f, 0.f, 0.f);
        *(float4*)&hs[r * HS + c4 * 4] = v;
    }
    __syncthreads();

    int tx = tid & 15, ty = tid >> 4;
    int cb = tx * 8;       // 8-column chunk (4 col-pairs)
    int rb = ty * 4;       // 4-row chunk

    unsigned long long acc[4][4];  // [row][colpair], each = 2 packed fp32
#pragma unroll
    for (int r = 0; r < 4; r++)
#pragma unroll
        for (int c = 0; c < 4; c++) acc[r][c] = 0ULL;  // = {0.0f, 0.0f}

    const float* h0p = &hs[(rb + 0) * HS];
    const float* h1p = &hs[(rb + 1) * HS];
    const float* h2p = &hs[(rb + 2) * HS];
    const float* h3p = &hs[(rb + 3) * HS];

#pragma unroll 2
    for (int k = 0; k < D; k++) {
        const unsigned long long* wp = (const unsigned long long*)&ws[k * 128 + cb];
        unsigned long long w0 = wp[0], w1 = wp[1], w2 = wp[2], w3 = wp[3];
        unsigned long long hd0 = f32x2_dup(h0p[k]);
        unsigned long long hd1 = f32x2_dup(h1p[k]);
        unsigned long long hd2 = f32x2_dup(h2p[k]);
        unsigned long long hd3 = f32x2_dup(h3p[k]);
        acc[0][0] = f32x2_fma(hd0, w0, acc[0][0]);
        acc[0][1] = f32x2_fma(hd0, w1, acc[0][1]);
        acc[0][2] = f32x2_fma(hd0, w2, acc[0][2]);
        acc[0][3] = f32x2_fma(hd0, w3, acc[0][3]);
        acc[1][0] = f32x2_fma(hd1, w0, acc[1][0]);
        acc[1][1] = f32x2_fma(hd1, w1, acc[1][1]);
        acc[1][2] = f32x2_fma(hd1, w2, acc[1][2]);
        acc[1][3] = f32x2_fma(hd1, w3, acc[1][3]);
        acc[2][0] = f32x2_fma(hd2, w0, acc[2][0]);
        acc[2][1] = f32x2_fma(hd2, w1, acc[2][1]);
        acc[2][2] = f32x2_fma(hd2, w2, acc[2][2]);
        acc[2][3] = f32x2_fma(hd2, w3, acc[2][3]);
        acc[3][0] = f32x2_fma(hd3, w0, acc[3][0]);
        acc[3][1] = f32x2_fma(hd3, w1, acc[3][1]);
        acc[3][2] = f32x2_fma(hd3, w2, acc[3][2]);
        acc[3][3] = f32x2_fma(hd3, w3, acc[3][3]);
    }

    float omb = 1.0f - beta;
    float* __restrict__ outp = out_base ? (out_base + (size_t)g * n * D) : g_feat[g];
    float4 ba = __ldg((const float4*)&bias[cb]);
    float4 bb4 = __ldg((const float4*)&bias[cb + 4]);
    float bias8[8] = {ba.x, ba.y, ba.z, ba.w, bb4.x, bb4.y, bb4.z, bb4.w};
#pragma unroll
    for (int r = 0; r < 4; r++) {
        int grow = row0 + rb + r;
        if (grow < n) {
            const float* hr = &hs[(rb + r) * HS + cb];
            float res[8];
#pragma unroll
            for (int c = 0; c < 4; c++) {
                float lo, hi;
                f32x2_unpack(acc[r][c], lo, hi);
                res[c * 2 + 0] = lo;
                res[c * 2 + 1] = hi;
            }
            float4 o0, o1;
            o0.x = fmaxf(fmaf(beta, res[0], omb * hr[0]) + bias8[0], 0.f);
            o0.y = fmaxf(fmaf(beta, res[1], omb * hr[1]) + bias8[1], 0.f);
            o0.z = fmaxf(fmaf(beta, res[2], omb * hr[2]) + bias8[2], 0.f);
            o0.w = fmaxf(fmaf(beta, res[3], omb * hr[3]) + bias8[3], 0.f);
            o1.x = fmaxf(fmaf(beta, res[4], omb * hr[4]) + bias8[4], 0.f);
            o1.y = fmaxf(fmaf(beta, res[5], omb * hr[5]) + bias8[5], 0.f);
            o1.z = fmaxf(fmaf(beta, res[6], omb * hr[6]) + bias8[6], 0.f);
            o1.w = fmaxf(fmaf(beta, res[7], omb * hr[7]) + bias8[7], 0.f);
            *(float4*)&outp[(size_t)grow * D + cb]     = o0;
            *(float4*)&outp[(size_t)grow * D + cb + 4] = o1;
        }
    }
}

// ---------------- standardization ----------------
__global__ void k_stats(const float* __restrict__ x, int g, int n) {
    int col = threadIdx.x;  // 128 threads
    int rows_per_block = (n + gridDim.x - 1) / gridDim.x;
    int r0 = blockIdx.x * rows_per_block;
    int r1 = min(r0 + rows_per_block, n);
    double ds = 0.0, ds2 = 0.0;
    for (int r = r0; r < r1; r++) {
        float v = x[(size_t)r * D + col];
        ds += (double)v;
        ds2 += (double)v * (double)v;
    }
    atomicAdd(&g_sum[g][col], ds);
    atomicAdd(&g_sumsq[g][col], ds2);
}

__global__ void k_finalize(int n) {
    int i = threadIdx.x;  // 256 threads = 2 graphs x 128 cols
    int g = i >> 7, c = i & 127;
    double s = g_sum[g][c], s2 = g_sumsq[g][c];
    double mean = s / n;
    double var = (s2 - s * s / (double)n) / (double)(n - 1);
    float sd = (float)sqrt(var > 0.0 ? var : 0.0);
    g_mean[g][c] = (float)mean;
    g_rstd[g][c] = 1.0f / fmaxf(sd, 1e-12f);
}

__global__ void k_norm(float* __restrict__ out, int n) {
    int i = blockIdx.x * blockDim.x + threadIdx.x;
    int total = 2 * n * D;
    if (i >= total) return;
    int g = (i >= n * D) ? 1 : 0;
    int c = i & 127;
    out[i] = (out[i] - g_mean[g][c]) * g_rstd[g][c];
}

// ---------------- launch ----------------
extern "C" void kernel_launch(void* const* d_in, const int* in_sizes, int n_in,
                              void* d_out, int out_size) {
    const float* feat1   = (const float*)d_in[0];
    const float* feat2   = (const float*)d_in[1];
    const int*   src1    = (const int*)d_in[2];
    const int*   dst1    = (const int*)d_in[3];
    const int*   src2    = (const int*)d_in[4];
    const int*   dst2    = (const int*)d_in[5];
    const float* weights = (const float*)d_in[6];
    const float* biases  = (const float*)d_in[7];
    float* out = (float*)d_out;

    int n = in_sizes[0] / D;
    int E = in_sizes[2];
    int L = in_sizes[6] / (D * D);
    int bpg = (n + RB - 1) / RB;

    // opt in to >48KB dynamic smem for the GEMM (non-stream call; capture-safe)
    cudaFuncSetAttribute(k_gemm, cudaFuncAttributeMaxDynamicSharedMemorySize,
                         GEMM_SMEM_BYTES);

    k_init<<<(n + 255) / 256, 256>>>(n);
    k_hist<<<(2 * E + 255) / 256, 256>>>(dst1, dst2, E);
    k_scan<<<2, 1024>>>(n);
    k_fill<<<(2 * E + 255) / 256, 256>>>(src1, dst1, src2, dst2, E);

    for (int l = 0; l < L; l++) {
        const float* e1 = (l == 0) ? feat1 : nullptr;
        const float* e2 = (l == 0) ? feat2 : nullptr;
        k_agg<<<(2 * n * 32 + 255) / 256, 256>>>(e1, e2, feat1, feat2, n);

        float beta = (float)log(1.0 / (double)(l + 1) + 1.0);
        float* gout = (l == L - 1) ? out : nullptr;
        k_gemm<<<2 * bpg, 256, GEMM_SMEM_BYTES>>>(
            weights + (size_t)l * D * D, biases + (size_t)l * D, beta, gout, n, bpg);
    }

    k_stats<<<512, 128>>>(out, 0, n);
    k_stats<<<512, 128>>>(out + (size_t)n * D, 1, n);
    k_finalize<<<1, 256>>>(n);
    k_norm<<<(2 * n * D + 255) / 256, 256>>>(out, n);
}

// round 7
// speedup vs baseline: 5.0143x; 1.3307x over previous
#include <cuda_runtime.h>
#include <math.h>

#define NN   100000
#define D    128
#define EMAX 1600000

// ---------------- scratch (device globals; no allocation allowed) ----------------
__device__ int    g_cnt[2][NN];
__device__ int    g_fill[2][NN];
__device__ int    g_rowptr[2][NN + 1];
__device__ int    g_esrc[2][EMAX];
__device__ float  g_norm[2][NN];
__device__ float  g_feat[2][NN * D];
__device__ float  g_h[2][NN * D];
__device__ double g_sum[2][D];
__device__ double g_sumsq[2][D];
__device__ float  g_mean[2][D];
__device__ float  g_rstd[2][D];

// ---------------- tf32 split helpers ----------------
__device__ __forceinline__ unsigned tf32_hi(float x) {
    unsigned r;
    asm("cvt.rna.tf32.f32 %0, %1;" : "=r"(r) : "f"(x));
    return r;
}
// Dekker split: hi = RN-to-tf32(x) (11-bit mantissa), lo = x - hi (exact in fp32)
__device__ __forceinline__ void tf32_split(float x, unsigned& hi, unsigned& lo) {
    hi = tf32_hi(x);
    lo = __float_as_uint(x - __uint_as_float(hi));
}
__device__ __forceinline__ void mma_tf32(float c[4], const unsigned a[4], const unsigned b[2]) {
    asm volatile(
        "mma.sync.aligned.m16n8k8.row.col.f32.tf32.tf32.f32 "
        "{%0,%1,%2,%3}, {%4,%5,%6,%7}, {%8,%9}, {%0,%1,%2,%3};\n"
        : "+f"(c[0]), "+f"(c[1]), "+f"(c[2]), "+f"(c[3])
        : "r"(a[0]), "r"(a[1]), "r"(a[2]), "r"(a[3]), "r"(b[0]), "r"(b[1]));
}

// ---------------- prep kernels ----------------
__global__ void k_init(int n) {
    int i = blockIdx.x * blockDim.x + threadIdx.x;
    if (i < n) {
        g_cnt[0][i] = 0; g_cnt[1][i] = 0;
        g_fill[0][i] = 0; g_fill[1][i] = 0;
    }
    if (i < D) {
        g_sum[0][i] = 0.0; g_sum[1][i] = 0.0;
        g_sumsq[0][i] = 0.0; g_sumsq[1][i] = 0.0;
    }
}

__global__ void k_hist(const int* __restrict__ dst1, const int* __restrict__ dst2, int E) {
    int i = blockIdx.x * blockDim.x + threadIdx.x;
    if (i < E) {
        atomicAdd(&g_cnt[0][dst1[i]], 1);
    } else if (i < 2 * E) {
        atomicAdd(&g_cnt[1][dst2[i - E]], 1);
    }
}

__global__ void k_scan(int n) {
    int g = blockIdx.x;
    __shared__ int warp_tot[32];
    __shared__ int s_off;
    int lane = threadIdx.x & 31;
    int wid = threadIdx.x >> 5;
    if (threadIdx.x == 0) s_off = 0;
    __syncthreads();
    for (int base = 0; base < n; base += 1024) {
        int i = base + threadIdx.x;
        int v = (i < n) ? g_cnt[g][i] : 0;
        if (i < n) g_norm[g][i] = rsqrtf((float)max(v, 1));
        int x = v;
#pragma unroll
        for (int ofs = 1; ofs < 32; ofs <<= 1) {
            int t = __shfl_up_sync(0xFFFFFFFFu, x, ofs);
            if (lane >= ofs) x += t;
        }
        if (lane == 31) warp_tot[wid] = x;
        __syncthreads();
        if (wid == 0) {
            int wt = warp_tot[lane];
            int y = wt;
#pragma unroll
            for (int ofs = 1; ofs < 32; ofs <<= 1) {
                int t = __shfl_up_sync(0xFFFFFFFFu, y, ofs);
                if (lane >= ofs) y += t;
            }
            warp_tot[lane] = y - wt;
        }
        __syncthreads();
        int excl = s_off + warp_tot[wid] + (x - v);
        if (i < n) g_rowptr[g][i] = excl;
        __syncthreads();
        if (threadIdx.x == 1023) s_off = excl + v;
        __syncthreads();
    }
    if (threadIdx.x == 0) g_rowptr[g][n] = s_off;
}

__global__ void k_fill(const int* __restrict__ src1, const int* __restrict__ dst1,
                       const int* __restrict__ src2, const int* __restrict__ dst2, int E) {
    int i = blockIdx.x * blockDim.x + threadIdx.x;
    if (i < E) {
        int d = dst1[i];
        int pos = g_rowptr[0][d] + atomicAdd(&g_fill[0][d], 1);
        g_esrc[0][pos] = src1[i];
    } else if (i < 2 * E) {
        int e = i - E;
        int d = dst2[e];
        int pos = g_rowptr[1][d] + atomicAdd(&g_fill[1][d], 1);
        g_esrc[1][pos] = src2[e];
    }
}

// ---------------- aggregation: warp per node, both graphs in one launch ----------------
__global__ void k_agg(const float* __restrict__ ext1, const float* __restrict__ ext2,
                      const float* __restrict__ feat01, const float* __restrict__ feat02,
                      int n) {
    int gw = (blockIdx.x * blockDim.x + threadIdx.x) >> 5;
    if (gw >= 2 * n) return;
    int g = (gw >= n) ? 1 : 0;
    int node = gw - g * n;
    int lane = threadIdx.x & 31;

    const float* __restrict__ fin = ext1 ? (g ? ext2 : ext1) : g_feat[g];
    const float* __restrict__ feat0 = g ? feat02 : feat01;
    const int*   __restrict__ rp  = g_rowptr[g];
    const int*   __restrict__ es  = g_esrc[g];
    const float* __restrict__ nrm = g_norm[g];

    int s = rp[node], e = rp[node + 1];
    float ax = 0.f, ay = 0.f, az = 0.f, aw = 0.f;

    int i = s;
    for (; i + 4 <= e; i += 4) {
        int s0 = __ldg(&es[i + 0]), s1 = __ldg(&es[i + 1]);
        int s2 = __ldg(&es[i + 2]), s3 = __ldg(&es[i + 3]);
        float n0 = __ldg(&nrm[s0]), n1 = __ldg(&nrm[s1]);
        float n2 = __ldg(&nrm[s2]), n3 = __ldg(&nrm[s3]);
        float4 v0 = __ldg((const float4*)&fin[(size_t)s0 * D + lane * 4]);
        float4 v1 = __ldg((const float4*)&fin[(size_t)s1 * D + lane * 4]);
        float4 v2 = __ldg((const float4*)&fin[(size_t)s2 * D + lane * 4]);
        float4 v3 = __ldg((const float4*)&fin[(size_t)s3 * D + lane * 4]);
        ax = fmaf(v0.x, n0, ax); ay = fmaf(v0.y, n0, ay); az = fmaf(v0.z, n0, az); aw = fmaf(v0.w, n0, aw);
        ax = fmaf(v1.x, n1, ax); ay = fmaf(v1.y, n1, ay); az = fmaf(v1.z, n1, az); aw = fmaf(v1.w, n1, aw);
        ax = fmaf(v2.x, n2, ax); ay = fmaf(v2.y, n2, ay); az = fmaf(v2.z, n2, az); aw = fmaf(v2.w, n2, aw);
        ax = fmaf(v3.x, n3, ax); ay = fmaf(v3.y, n3, ay); az = fmaf(v3.z, n3, az); aw = fmaf(v3.w, n3, aw);
    }
    for (; i < e; i++) {
        int sv = __ldg(&es[i]);
        float nv = __ldg(&nrm[sv]);
        float4 v = __ldg((const float4*)&fin[(size_t)sv * D + lane * 4]);
        ax = fmaf(v.x, nv, ax); ay = fmaf(v.y, nv, ay);
        az = fmaf(v.z, nv, az); aw = fmaf(v.w, nv, aw);
    }

    float nd = nrm[node] * 0.9f;
    float4 f0 = __ldg((const float4*)&feat0[(size_t)node * D + lane * 4]);
    float4 o;
    o.x = fmaf(ax, nd, 0.1f * f0.x);
    o.y = fmaf(ay, nd, 0.1f * f0.y);
    o.z = fmaf(az, nd, 0.1f * f0.z);
    o.w = fmaf(aw, nd, 0.1f * f0.w);
    // streaming store: h is read exactly once (by k_gemm) — keep feat L2-resident
    __stcs((float4*)&g_h[g][(size_t)node * D + lane * 4], o);
}

// ---------------- GEMM via split-tf32 tensor-core MMA ----------------
// out = relu( h @ W' + bias ),  W' = beta*W + (1-beta)*I  (GCNII fold)
// Block: 512 threads (16 warps), tile 128 rows x 128 cols, K=128.
// Warp = 32x32 output. 2-term Dekker split, 3 MMAs per position (~fp32 accuracy).
#define HSST 132
#define WSST 136
#define GEMM_SMEM_BYTES ((128 * HSST + 128 * WSST) * (int)sizeof(float))  // 137,216 B
__global__ void __launch_bounds__(512, 1) k_gemm(const float* __restrict__ W,
                                                 const float* __restrict__ bias, float beta,
                                                 float* __restrict__ out_base, int n, int bpg) {
    extern __shared__ float smem_dyn[];
    float* hs = smem_dyn;               // [128][HSST]
    float* ws = smem_dyn + 128 * HSST;  // [128][WSST]  (W' = beta*W + (1-beta)*I)
    int g = (blockIdx.x >= bpg) ? 1 : 0;
    int row0 = (blockIdx.x - g * bpg) * 128;
    int tid = threadIdx.x;
    const float* __restrict__ hin = g_h[g];
    float omb = 1.0f - beta;

    // stage W' (fold beta scale + identity)
    const float4* __restrict__ W4 = (const float4*)W;
#pragma unroll
    for (int i = 0; i < 8; i++) {
        int idx = tid + i * 512;           // 4096 float4
        int k = idx >> 5, c4 = (idx & 31) << 2;
        float4 v = __ldg(&W4[idx]);
        v.x *= beta; v.y *= beta; v.z *= beta; v.w *= beta;
        int dk = k - c4;
        if (dk == 0) v.x += omb;
        else if (dk == 1) v.y += omb;
        else if (dk == 2) v.z += omb;
        else if (dk == 3) v.w += omb;
        *(float4*)&ws[k * WSST + c4] = v;
    }
    // stage h tile [128][128]
#pragma unroll
    for (int i = 0; i < 8; i++) {
        int idx = tid + i * 512;           // 4096 float4
        int r = idx >> 5, c4 = (idx & 31) << 2;
        int grow = row0 + r;
        float4 v = make_float4(0.f, 0.f, 0.f, 0.f);
        if (grow < n) v = __ldcs((const float4*)&hin[(size_t)grow * D + c4]);
        *(float4*)&hs[r * HSST + c4] = v;
    }
    __syncthreads();

    int lane = tid & 31, warp = tid >> 5;
    int gid = lane >> 2, tig = lane & 3;
    int wm = warp & 3, wn = warp >> 2;     // 4x4 warp grid
    int rowB = wm * 32, colB = wn * 32;

    float c[2][4][4];
#pragma unroll
    for (int mb = 0; mb < 2; mb++)
#pragma unroll
        for (int nb = 0; nb < 4; nb++)
#pragma unroll
            for (int q = 0; q < 4; q++) c[mb][nb][q] = 0.f;

#pragma unroll 4
    for (int ks = 0; ks < 16; ks++) {
        int k0 = ks * 8;
        unsigned ahi[2][4], alo[2][4];
#pragma unroll
        for (int mb = 0; mb < 2; mb++) {
            int r0 = (rowB + mb * 16 + gid) * HSST;
            int r1 = r0 + 8 * HSST;
            float x0 = hs[r0 + k0 + tig];
            float x1 = hs[r1 + k0 + tig];
            float x2 = hs[r0 + k0 + tig + 4];
            float x3 = hs[r1 + k0 + tig + 4];
            tf32_split(x0, ahi[mb][0], alo[mb][0]);
            tf32_split(x1, ahi[mb][1], alo[mb][1]);
            tf32_split(x2, ahi[mb][2], alo[mb][2]);
            tf32_split(x3, ahi[mb][3], alo[mb][3]);
        }
        unsigned bhi[4][2], blo[4][2];
#pragma unroll
        for (int nb = 0; nb < 4; nb++) {
            int cix = colB + nb * 8 + gid;
            float y0 = ws[(k0 + tig) * WSST + cix];
            float y1 = ws[(k0 + tig + 4) * WSST + cix];
            tf32_split(y0, bhi[nb][0], blo[nb][0]);
            tf32_split(y1, bhi[nb][1], blo[nb][1]);
        }
#pragma unroll
        for (int mb = 0; mb < 2; mb++)
#pragma unroll
            for (int nb = 0; nb < 4; nb++) {
                mma_tf32(c[mb][nb], ahi[mb], bhi[nb]);
                mma_tf32(c[mb][nb], ahi[mb], blo[nb]);
                mma_tf32(c[mb][nb], alo[mb], bhi[nb]);
            }
    }

    float* __restrict__ outp = out_base ? (out_base + (size_t)g * n * D) : g_feat[g];
#pragma unroll
    for (int nb = 0; nb < 4; nb++) {
        int col = colB + nb * 8 + tig * 2;
        float2 bb = *(const float2*)&bias[col];
#pragma unroll
        for (int mb = 0; mb < 2; mb++) {
            int r0g = row0 + rowB + mb * 16 + gid;
            int r1g = r0g + 8;
            if (r0g < n) {
                float2 o;
                o.x = fmaxf(c[mb][nb][0] + bb.x, 0.f);
                o.y = fmaxf(c[mb][nb][1] + bb.y, 0.f);
                *(float2*)&outp[(size_t)r0g * D + col] = o;
            }
            if (r1g < n) {
                float2 o;
                o.x = fmaxf(c[mb][nb][2] + bb.x, 0.f);
                o.y = fmaxf(c[mb][nb][3] + bb.y, 0.f);
                *(float2*)&outp[(size_t)r1g * D + col] = o;
            }
        }
    }
}

// ---------------- standardization (both graphs in one launch) ----------------
__global__ void k_stats(const float* __restrict__ x, int n, int bpg) {
    int g = (blockIdx.x >= bpg) ? 1 : 0;
    int blk = blockIdx.x - g * bpg;
    int col = threadIdx.x;  // 128 threads
    const float* __restrict__ xg = x + (size_t)g * n * D;
    int rows_per_block = (n + bpg - 1) / bpg;
    int r0 = blk * rows_per_block;
    int r1 = min(r0 + rows_per_block, n);
    double ds = 0.0, ds2 = 0.0;
    for (int r = r0; r < r1; r++) {
        float v = xg[(size_t)r * D + col];
        ds += (double)v;
        ds2 += (double)v * (double)v;
    }
    atomicAdd(&g_sum[g][col], ds);
    atomicAdd(&g_sumsq[g][col], ds2);
}

__global__ void k_finalize(int n) {
    int i = threadIdx.x;
    int g = i >> 7, c = i & 127;
    double s = g_sum[g][c], s2 = g_sumsq[g][c];
    double mean = s / n;
    double var = (s2 - s * s / (double)n) / (double)(n - 1);
    float sd = (float)sqrt(var > 0.0 ? var : 0.0);
    g_mean[g][c] = (float)mean;
    g_rstd[g][c] = 1.0f / fmaxf(sd, 1e-12f);
}

__global__ void k_norm(float* __restrict__ out, int n) {
    int i = blockIdx.x * blockDim.x + threadIdx.x;
    int total = 2 * n * D;
    if (i >= total) return;
    int g = (i >= n * D) ? 1 : 0;
    int c = i & 127;
    out[i] = (__ldcs(&out[i]) - g_mean[g][c]) * g_rstd[g][c];
}

// ---------------- launch ----------------
extern "C" void kernel_launch(void* const* d_in, const int* in_sizes, int n_in,
                              void* d_out, int out_size) {
    const float* feat1   = (const float*)d_in[0];
    const float* feat2   = (const float*)d_in[1];
    const int*   src1    = (const int*)d_in[2];
    const int*   dst1    = (const int*)d_in[3];
    const int*   src2    = (const int*)d_in[4];
    const int*   dst2    = (const int*)d_in[5];
    const float* weights = (const float*)d_in[6];
    const float* biases  = (const float*)d_in[7];
    float* out = (float*)d_out;

    int n = in_sizes[0] / D;
    int E = in_sizes[2];
    int L = in_sizes[6] / (D * D);
    int bpg = (n + 127) / 128;

    cudaFuncSetAttribute(k_gemm, cudaFuncAttributeMaxDynamicSharedMemorySize,
                         GEMM_SMEM_BYTES);

    k_init<<<(n + 255) / 256, 256>>>(n);
    k_hist<<<(2 * E + 255) / 256, 256>>>(dst1, dst2, E);
    k_scan<<<2, 1024>>>(n);
    k_fill<<<(2 * E + 255) / 256, 256>>>(src1, dst1, src2, dst2, E);

    for (int l = 0; l < L; l++) {
        const float* e1 = (l == 0) ? feat1 : nullptr;
        const float* e2 = (l == 0) ? feat2 : nullptr;
        k_agg<<<(2 * n * 32 + 255) / 256, 256>>>(e1, e2, feat1, feat2, n);

        float beta = (float)log(1.0 / (double)(l + 1) + 1.0);
        float* gout = (l == L - 1) ? out : nullptr;
        k_gemm<<<2 * bpg, 512, GEMM_SMEM_BYTES>>>(
            weights + (size_t)l * D * D, biases + (size_t)l * D, beta, gout, n, bpg);
    }

    k_stats<<<1024, 128>>>(out, n, 512);
    k_finalize<<<1, 256>>>(n);
    k_norm<<<(2 * n * D + 255) / 256, 256>>>(out, n);
}